// round 2
// baseline (speedup 1.0000x reference)
#include <cuda_runtime.h>

// GraphConvolution_LEGNN: out = 0.9 * rownorm1(A ⊙ same_class_mask) @ x + 0.1 * h0
// y is one-hot -> mask[i][j] = (label[i]==label[j]); A is 0/1.
// => out[i] = 0.9 * (sum_{j in same-class nbrs} A[i,j]*x[j]) / max(sum w,1e-12) + 0.1*h0[i]
//
// Inputs (metadata order): d_in[0]=x [N,F] f32, d_in[1]=A [N,N] f32,
//                          d_in[2]=h0 [N,F] f32, d_in[3]=y [N,C] f32
// Output: f32 [N,F]

#define N_NODES 10000
#define F_DIM   256
#define C_CLS   16
#define CAP     1024   // per-row neighbor list capacity (expected ~6, worst ~40)

__device__ int g_labels[N_NODES];

__global__ void labels_kernel(const float* __restrict__ y) {
    int i = blockIdx.x * blockDim.x + threadIdx.x;
    if (i >= N_NODES) return;
    const float* yr = y + (size_t)i * C_CLS;
    int lab = 0;
    float best = yr[0];
#pragma unroll
    for (int c = 1; c < C_CLS; ++c) {
        float v = yr[c];
        if (v > best) { best = v; lab = c; }
    }
    g_labels[i] = lab;
}

__global__ __launch_bounds__(F_DIM)
void gcn_row_kernel(const float* __restrict__ x,
                    const float* __restrict__ A,
                    const float* __restrict__ h0,
                    float* __restrict__ out) {
    __shared__ int   s_idx[CAP];
    __shared__ float s_val[CAP];
    __shared__ int   s_cnt;

    const int row = blockIdx.x;
    const int tid = threadIdx.x;

    if (tid == 0) s_cnt = 0;
    __syncthreads();

    const int myc = g_labels[row];

    // Stream this row of A with float4 loads; push matching nonzeros to shared list.
    // N_NODES = 10000 = 2500 float4; row byte offset 40000*row is 16B-aligned.
    const float4* __restrict__ Arow =
        reinterpret_cast<const float4*>(A + (size_t)row * N_NODES);
    const int n4 = N_NODES / 4;  // 2500

    for (int j4 = tid; j4 < n4; j4 += F_DIM) {
        float4 a = Arow[j4];
        int base = j4 << 2;
#pragma unroll
        for (int k = 0; k < 4; ++k) {
            float av = (k == 0) ? a.x : (k == 1) ? a.y : (k == 2) ? a.z : a.w;
            if (av != 0.0f) {
                int col = base + k;
                if (g_labels[col] == myc) {
                    int p = atomicAdd(&s_cnt, 1);
                    if (p < CAP) {  // safety; statistically never exceeded
                        s_idx[p] = col;
                        s_val[p] = av;
                    }
                }
            }
        }
    }
    __syncthreads();

    const int cnt = min(s_cnt, CAP);

    // Drain: each thread owns one feature column (F == blockDim).
    float acc = 0.0f, sumw = 0.0f;
    int k = 0;
    for (; k + 4 <= cnt; k += 4) {  // unrolled for load MLP
        int   c0 = s_idx[k],     c1 = s_idx[k + 1];
        int   c2 = s_idx[k + 2], c3 = s_idx[k + 3];
        float w0 = s_val[k],     w1 = s_val[k + 1];
        float w2 = s_val[k + 2], w3 = s_val[k + 3];
        float v0 = x[(size_t)c0 * F_DIM + tid];
        float v1 = x[(size_t)c1 * F_DIM + tid];
        float v2 = x[(size_t)c2 * F_DIM + tid];
        float v3 = x[(size_t)c3 * F_DIM + tid];
        acc  += w0 * v0 + w1 * v1 + w2 * v2 + w3 * v3;
        sumw += w0 + w1 + w2 + w3;
    }
    for (; k < cnt; ++k) {
        float w = s_val[k];
        acc  += w * x[(size_t)s_idx[k] * F_DIM + tid];
        sumw += w;
    }

    float rs = fmaxf(sumw, 1e-12f);
    size_t o = (size_t)row * F_DIM + tid;
    out[o] = 0.9f * (acc / rs) + 0.1f * h0[o];
}

extern "C" void kernel_launch(void* const* d_in, const int* in_sizes, int n_in,
                              void* d_out, int out_size) {
    const float* x  = (const float*)d_in[0];
    const float* A  = (const float*)d_in[1];
    const float* h0 = (const float*)d_in[2];
    const float* y  = (const float*)d_in[3];
    float* out = (float*)d_out;

    labels_kernel<<<(N_NODES + 255) / 256, 256>>>(y);
    gcn_row_kernel<<<N_NODES, F_DIM>>>(x, A, h0, out);
}

// round 3
// speedup vs baseline: 1.5059x; 1.5059x over previous
#include <cuda_runtime.h>

// GraphConvolution_LEGNN: out = 0.9 * rownorm1(A ⊙ same_class_mask) @ x + 0.1 * h0
// y one-hot -> mask[i][j] = (label[i]==label[j]); A ∈ {0,1}.
// Key opt (R2): only same-class columns of A can contribute. Precompute per-class
// column lists; each row gathers just ~N/C=625 scattered A entries instead of
// streaming the full 40KB row. Sector math: ~16KB touched per row vs 40KB -> 2.5x
// less DRAM traffic on the dominant A stream.
//
// Inputs: d_in[0]=x [N,F] f32, d_in[1]=A [N,N] f32, d_in[2]=h0 [N,F] f32,
//         d_in[3]=y [N,C] f32.  Output: f32 [N,F].

#define N_NODES 10000
#define F_DIM   256
#define C_CLS   16
#define CAP     1024   // per-row neighbor capacity (expected ~6, worst ~40)

__device__ int g_labels[N_NODES];
__device__ int g_ccnt[C_CLS];
__device__ int g_cols[C_CLS * N_NODES];   // per-class column lists (c*N .. c*N+cnt)

__global__ void labels_kernel(const float* __restrict__ y) {
    int i = blockIdx.x * blockDim.x + threadIdx.x;
    if (i < C_CLS) g_ccnt[i] = 0;          // zero counts before build pass
    if (i >= N_NODES) return;
    const float* yr = y + (size_t)i * C_CLS;
    int lab = 0;
    float best = yr[0];
#pragma unroll
    for (int c = 1; c < C_CLS; ++c) {
        float v = yr[c];
        if (v > best) { best = v; lab = c; }
    }
    g_labels[i] = lab;
}

__global__ void build_lists_kernel() {
    int i = blockIdx.x * blockDim.x + threadIdx.x;
    if (i >= N_NODES) return;
    int lab = g_labels[i];
    int p = atomicAdd(&g_ccnt[lab], 1);
    g_cols[lab * N_NODES + p] = i;
}

__global__ __launch_bounds__(F_DIM)
void gcn_row_kernel(const float* __restrict__ x,
                    const float* __restrict__ A,
                    const float* __restrict__ h0,
                    float* __restrict__ out) {
    __shared__ int   s_idx[CAP];
    __shared__ float s_val[CAP];
    __shared__ int   s_cnt;

    const int row = blockIdx.x;
    const int tid = threadIdx.x;

    if (tid == 0) s_cnt = 0;
    __syncthreads();

    const int myc  = g_labels[row];
    const int ccnt = g_ccnt[myc];
    const int* __restrict__ clist = g_cols + myc * N_NODES;
    const float* __restrict__ Arow = A + (size_t)row * N_NODES;

    // Gather only same-class columns of this A row (~625 scattered LDG.32).
    // Class list is L2-resident & broadcast across CTAs; A read streaming (.cs).
    for (int k = tid; k < ccnt; k += F_DIM) {
        int col  = __ldg(&clist[k]);
        float av = __ldcs(&Arow[col]);
        if (av != 0.0f) {
            int p = atomicAdd(&s_cnt, 1);
            if (p < CAP) {
                s_idx[p] = col;
                s_val[p] = av;
            }
        }
    }
    __syncthreads();

    const int cnt = min(s_cnt, CAP);

    // Drain: thread tid owns feature column tid (F == blockDim).
    float acc = 0.0f, sumw = 0.0f;
    int k = 0;
    for (; k + 4 <= cnt; k += 4) {
        int   c0 = s_idx[k],     c1 = s_idx[k + 1];
        int   c2 = s_idx[k + 2], c3 = s_idx[k + 3];
        float w0 = s_val[k],     w1 = s_val[k + 1];
        float w2 = s_val[k + 2], w3 = s_val[k + 3];
        float v0 = __ldg(&x[(size_t)c0 * F_DIM + tid]);
        float v1 = __ldg(&x[(size_t)c1 * F_DIM + tid]);
        float v2 = __ldg(&x[(size_t)c2 * F_DIM + tid]);
        float v3 = __ldg(&x[(size_t)c3 * F_DIM + tid]);
        acc  += w0 * v0 + w1 * v1 + w2 * v2 + w3 * v3;
        sumw += w0 + w1 + w2 + w3;
    }
    for (; k < cnt; ++k) {
        float w = s_val[k];
        acc  += w * __ldg(&x[(size_t)s_idx[k] * F_DIM + tid]);
        sumw += w;
    }

    float rs = fmaxf(sumw, 1e-12f);
    size_t o = (size_t)row * F_DIM + tid;
    out[o] = 0.9f * (acc / rs) + 0.1f * h0[o];
}

extern "C" void kernel_launch(void* const* d_in, const int* in_sizes, int n_in,
                              void* d_out, int out_size) {
    const float* x  = (const float*)d_in[0];
    const float* A  = (const float*)d_in[1];
    const float* h0 = (const float*)d_in[2];
    const float* y  = (const float*)d_in[3];
    float* out = (float*)d_out;

    labels_kernel<<<(N_NODES + 255) / 256, 256>>>(y);
    build_lists_kernel<<<(N_NODES + 255) / 256, 256>>>();
    gcn_row_kernel<<<N_NODES, F_DIM>>>(x, A, h0, out);
}